// round 7
// baseline (speedup 1.0000x reference)
#include <cuda_runtime.h>
#include <math.h>

#define NB        1024
#define LSCALE    128.0f
#define KPRE      300
#define KOUT      10
#define SEGSZ     384          // 8 segments x 384 = 3072 cache entries
#define CANDCAP   640
#define SORTN     1024
#define RAW_T0    420          // first-band overshoot (valid-rate slack)

struct Ptrs {
    const float* cls[4];
    const float* box[4];
    const float* anc[4];
};

// One CTA per (batch, level): stream cls (branch-free common path) ->
// floored histogram + segmented smem cache -> exact top-K cut -> decode band
// -> 1024-wide bitonic sort (key = score|~ancidx|slot, preserves lax.top_k
// tie order) -> register NMS.
__global__ __launch_bounds__(1024) void detect_kernel(Ptrs P, float* out, int out_size) {
    const int img = blockIdx.x;
    const int b   = img >> 2;
    const int lvl = img & 3;
    const int HW  = 16384 >> (2*lvl);          // 16384,4096,1024,256
    const int N   = 9 * HW;
    // cache floor bucket per level (expected above-floor counts ~2k-2.5k << 3072)
    const int flBK = (lvl==0) ? 281 : (lvl==1) ? 192 : (lvl==2) ? 128 : 0;
    const float floorVal = (float)flBK * (1.0f/128.0f);   // exact: x*128 exact
    const float* cls  = P.cls[lvl] + (size_t)b * N;
    const float* boxp = P.box[lvl];
    const float* anc  = P.anc[lvl];
    const int tid = threadIdx.x, wid = tid >> 5, lane = tid & 31;

    __shared__ int   hist[NB];
    __shared__ float cval[8*SEGSZ];
    __shared__ int   cidx[8*SEGSZ];
    __shared__ unsigned long long candKey[SORTN];
    __shared__ float4 candBox[CANDCAP];
    __shared__ int   wtot[32];
    __shared__ int   s_seg[8];
    __shared__ int   s_cnt, s_cut, s_next, s_nk;
    __shared__ unsigned keepw[10];

    const bool vF = (out_size >= 3840);
    unsigned char* vB = (unsigned char*)out + 12800;
    const int slot0 = b*40 + lvl*10;

    // zero this CTA's output region (d_out is poisoned)
    {
        int base5 = b*200 + lvl*50;
        if (tid < 50) out[base5 + tid] = 0.0f;
        if (tid >= 64 && tid < 74) {
            int k = tid - 64;
            if (vF) out[3200 + slot0 + k] = 0.0f;
            else    vB[slot0 + k] = 0;
        }
    }
    hist[tid] = 0;
    if (tid < 8) s_seg[tid] = 0;
    if (tid == 0) s_cnt = 0;
    __syncthreads();

    const int n4 = N >> 2;
    const float4* cls4 = (const float4*)cls;
    const int seg = wid & 7;

    // above-floor predicate, exact vs bucket test
    auto above_floor = [&](float x) -> bool {
        return (flBK == 0) ? (x > 0.0f) : (x >= floorVal);
    };

    // pass 1: stream cls; common path = 3 FMNMX + 1 compare, no divergence.
    auto proc = [&](float4 v, int i4) {
        float m = fmaxf(fmaxf(v.x, v.y), fmaxf(v.z, v.w));
        if (above_floor(m)) {                 // rare, mostly warp-uniform
            float xs[4] = {v.x, v.y, v.z, v.w};
            #pragma unroll
            for (int c = 0; c < 4; c++) {
                float x = xs[c];
                if (above_floor(x)) {
                    int bk = (int)(x * LSCALE); bk = bk > NB-1 ? NB-1 : bk;
                    atomicAdd(&hist[bk], 1);
                    int p = atomicAdd(&s_seg[seg], 1);
                    if (p < SEGSZ) { cval[seg*SEGSZ + p] = x; cidx[seg*SEGSZ + p] = i4*4 + c; }
                }
            }
        }
    };
    {
        int i = tid;
        for (; i + 7*1024 < n4; i += 8*1024) {
            float4 v0 = cls4[i];          float4 v1 = cls4[i + 1024];
            float4 v2 = cls4[i + 2048];   float4 v3 = cls4[i + 3072];
            float4 v4 = cls4[i + 4096];   float4 v5 = cls4[i + 5120];
            float4 v6 = cls4[i + 6144];   float4 v7 = cls4[i + 7168];
            proc(v0, i);        proc(v1, i + 1024);
            proc(v2, i + 2048); proc(v3, i + 3072);
            proc(v4, i + 4096); proc(v5, i + 5120);
            proc(v6, i + 6144); proc(v7, i + 7168);
        }
        for (; i < n4; i += 1024) proc(cls4[i], i);
    }
    __syncthreads();

    bool cacheOK = true;
    #pragma unroll
    for (int s = 0; s < 8; s++) cacheOK = cacheOK && (s_seg[s] <= SEGSZ);

    // per-thread suffix count strictly after this thread's bucket
    auto computeAbove = [&]() -> int {
        __syncthreads();
        int h = hist[tid];
        int v = h;
        #pragma unroll
        for (int off = 1; off < 32; off <<= 1) {
            int t2 = __shfl_down_sync(0xFFFFFFFFu, v, off);
            if (lane + off < 32) v += t2;
        }
        if (lane == 0) wtot[wid] = v;
        __syncthreads();
        int tail = 0;
        for (int w = wid + 1; w < 32; w++) tail += wtot[w];
        return (v - h) + tail;
    };

    auto decode_store = [&](float x, int j) {
        int a = j / HW;
        int rem = j - a*HW;
        const float* bp = boxp + ((size_t)(b*9 + a) * 4) * HW + rem;
        float d0 = bp[0], d1 = bp[HW], d2 = bp[2*HW], d3 = bp[3*HW];
        float4 an = ((const float4*)anc)[j];
        float w = an.z - an.x, h = an.w - an.y;
        float cx = an.x + 0.5f*w, cy = an.y + 0.5f*h;
        d0 = fminf(fmaxf(d0, -2.0f), 2.0f);
        d1 = fminf(fmaxf(d1, -2.0f), 2.0f);
        d2 = fminf(fmaxf(d2, -2.0f), 2.0f);
        d3 = fminf(fmaxf(d3, -2.0f), 2.0f);
        float px = cx + d0*w, py = cy + d1*h;
        float pw = w * expf(d2), ph = h * expf(d3);
        float x1 = fminf(fmaxf(px - 0.5f*pw, 0.0f), 1024.0f);
        float y1 = fminf(fmaxf(py - 0.5f*ph, 0.0f), 1024.0f);
        float x2 = fminf(fmaxf(px + 0.5f*pw, 0.0f), 1024.0f);
        float y2 = fminf(fmaxf(py + 0.5f*ph, 0.0f), 1024.0f);
        float bw = x2 - x1, bh = y2 - y1;
        if (bw > 1.0f && bh > 1.0f && bw < 2000.0f && bh < 2000.0f) {
            int pos = atomicAdd(&s_cnt, 1);
            if (pos < CANDCAP) {
                unsigned lo = ((262143u - (unsigned)j) << 10) | (unsigned)pos;
                candKey[pos] = ((unsigned long long)__float_as_uint(x) << 32) | lo;
                candBox[pos] = make_float4(x1, y1, x2, y2);
            }
        }
    };

    int above = computeAbove();
    bool histFull = (flBK == 0);
    int curCut = NB;
    int rawTarget = RAW_T0;
    while (true) {
        if (tid == 0) s_cut = 0;
        __syncthreads();
        // crossing bucket: unique tid with suffix>=target but strictly-after<target
        {
            int cum = above + hist[tid];
            if (tid < curCut && cum >= rawTarget && above < rawTarget) s_cut = tid;
        }
        __syncthreads();
        int newCut = s_cut;

        if (!histFull && newCut < flBK) {
            // cold path: extend histogram below the floor (exactness guard)
            for (int i = tid; i < n4; i += 1024) {
                float4 v = cls4[i];
                float xs[4] = {v.x, v.y, v.z, v.w};
                for (int c = 0; c < 4; c++) {
                    float x = xs[c];
                    if (x > 0.0f && !above_floor(x)) {
                        int bk = (int)(x * LSCALE); bk = bk > NB-1 ? NB-1 : bk;
                        atomicAdd(&hist[bk], 1);
                    }
                }
            }
            histFull = true;
            above = computeAbove();
            continue;
        }

        if (cacheOK && newCut >= flBK) {
            // collect band [newCut, curCut) from smem cache segments
            for (int t = tid; t < 8*SEGSZ; t += 1024) {
                int sg = t / SEGSZ, o = t - sg*SEGSZ;
                if (o < s_seg[sg]) {
                    float x = cval[t];
                    int bk = (int)(x * LSCALE); bk = bk > NB-1 ? NB-1 : bk;
                    if (bk >= newCut && bk < curCut) decode_store(x, cidx[t]);
                }
            }
        } else {
            // exact fallback: rescan global for the band
            for (int i = tid; i < n4; i += 1024) {
                float4 v = cls4[i];
                float xs[4] = {v.x, v.y, v.z, v.w};
                for (int c = 0; c < 4; c++) {
                    float x = xs[c];
                    if (x > 0.0f) {
                        int bk = (int)(x * LSCALE); bk = bk > NB-1 ? NB-1 : bk;
                        if (bk >= newCut && bk < curCut) decode_store(x, i*4 + c);
                    }
                }
            }
        }
        __syncthreads();
        int cnt = s_cnt;
        curCut = newCut;
        if (cnt >= KPRE || curCut == 0) break;
        rawTarget += (KPRE - cnt) + 32;   // valid shortfall -> extend band
        __syncthreads();
    }

    int scnt = s_cnt < CANDCAP ? s_cnt : CANDCAP;
    if (tid >= scnt) candKey[tid] = 0ull;
    __syncthreads();

    // bitonic sort, descending, 1024 elems / 1024 threads (uniform, no guards)
    {
        unsigned long long key = candKey[tid];
        __syncthreads();
        #pragma unroll
        for (int k = 2; k <= SORTN; k <<= 1) {
            bool segDesc = ((tid & k) == 0);
            #pragma unroll
            for (int j = k >> 1; j > 0; j >>= 1) {
                unsigned long long okey;
                if (j >= 32) {
                    candKey[tid] = key;
                    __syncthreads();
                    okey = candKey[tid ^ j];
                    __syncthreads();
                } else {
                    unsigned hi = __shfl_xor_sync(0xFFFFFFFFu, (unsigned)(key >> 32), j);
                    unsigned lo = __shfl_xor_sync(0xFFFFFFFFu, (unsigned)key, j);
                    okey = ((unsigned long long)hi << 32) | lo;
                }
                bool keepMax = (((tid & j) == 0) == segDesc);
                bool take = keepMax ? (okey > key) : (okey < key);
                if (take) key = okey;
            }
        }
        candKey[tid] = key;
        __syncthreads();
    }

    // NMS: each thread holds its candidate's box in registers
    const int m = scnt < KPRE ? scnt : KPRE;
    float mx1 = 0, my1 = 0, mx2 = 0, my2 = 0, mar = 0;
    if (tid < m) {
        unsigned long long kk = candKey[tid];
        float4 bb = candBox[(int)(kk & 1023u)];
        mx1 = bb.x; my1 = bb.y; mx2 = bb.z; my2 = bb.w;
        mar = (bb.z - bb.x) * (bb.w - bb.y);
    }
    if (tid < 10) {
        int lo = tid * 32;
        unsigned w;
        if (m >= lo + 32) w = 0xFFFFFFFFu;
        else if (m > lo)  w = (1u << (m - lo)) - 1u;
        else              w = 0u;
        keepw[tid] = w;
    }
    if (tid == 0) s_nk = 0;
    __syncthreads();

    // one round per kept box (<=10); exact: later keeps cannot alter prefix
    for (int round = 0; round <= KOUT; round++) {
        if (tid < 32) {
            unsigned v = (tid < 10) ? keepw[tid] : 0u;
            unsigned nz = __ballot_sync(0xFFFFFFFFu, v != 0u);
            int w = __ffs(nz) - 1;
            unsigned vw = __shfl_sync(0xFFFFFFFFu, v, (w < 0) ? 0 : w);
            if (tid == 0) s_next = nz ? (w*32 + __ffs(vw) - 1) : -1;
        }
        __syncthreads();
        int i = s_next;
        if (i < 0 || s_nk >= KOUT) break;

        unsigned long long ki = candKey[i];            // broadcast
        float4 bi = candBox[(int)(ki & 1023u)];        // broadcast
        float ba = (bi.z - bi.x) * (bi.w - bi.y);

        if (tid == 0) {
            int nk = s_nk;
            float logit = __uint_as_float((unsigned)(ki >> 32));
            float sc = 1.0f / (1.0f + expf(-logit));
            int s5 = b*200 + (lvl*10 + nk)*5;
            out[s5+0] = bi.x; out[s5+1] = bi.y;
            out[s5+2] = bi.z; out[s5+3] = bi.w;
            out[s5+4] = sc;
            if (vF) out[3200 + slot0 + nk] = 1.0f;
            else    vB[slot0 + nk] = 1;
            s_nk = nk + 1;
            atomicAnd(&keepw[i >> 5], ~(1u << (i & 31)));
        }
        if (tid > i && tid < m && ((keepw[tid >> 5] >> (tid & 31)) & 1u)) {
            float ix1 = fmaxf(bi.x, mx1), iy1 = fmaxf(bi.y, my1);
            float ix2 = fminf(bi.z, mx2), iy2 = fminf(bi.w, my2);
            float iw = fmaxf(ix2 - ix1, 0.0f), ih = fmaxf(iy2 - iy1, 0.0f);
            float inter = iw * ih;
            float iou = inter / (ba + mar - inter + 1e-9f);
            if (iou > 0.3f) atomicAnd(&keepw[tid >> 5], ~(1u << (tid & 31)));
        }
        __syncthreads();
    }
}

// ---------------------------------------------------------------------------
extern "C" void kernel_launch(void* const* d_in, const int* in_sizes, int n_in,
                              void* d_out, int out_size) {
    Ptrs P;
    if (n_in >= 2 && in_sizes[0] == 2359296 && in_sizes[1] == 9437184) {
        for (int l = 0; l < 4; l++) {
            P.cls[l] = (const float*)d_in[3*l + 0];
            P.box[l] = (const float*)d_in[3*l + 1];
            P.anc[l] = (const float*)d_in[3*l + 2];
        }
    } else if (n_in >= 1 && in_sizes[0] == 2359296) {
        for (int l = 0; l < 4; l++) {
            P.cls[l] = (const float*)d_in[l];
            P.box[l] = (const float*)d_in[4 + l];
            P.anc[l] = (const float*)d_in[8 + l];
        }
    } else {
        for (int l = 0; l < 4; l++) {
            P.anc[l] = (const float*)d_in[l];
            P.box[l] = (const float*)d_in[4 + l];
            P.cls[l] = (const float*)d_in[8 + l];
        }
    }
    detect_kernel<<<64, 1024>>>(P, (float*)d_out, out_size);
}